// round 9
// baseline (speedup 1.0000x reference)
#include <cuda_runtime.h>
#include <cuda_fp16.h>

#define N_NODES 8192
#define N_EDGES 262144
#define NH 8
#define IN_DIM 128
#define HC 1024
#define TOTAL_E (N_EDGES + N_NODES)     // 270336, divisible by 4
#define NA (N_NODES * NH)

#define NBLK 592
#define NTHR 256
#define TOTNT (NBLK * NTHR)
#define EPT 4
#define QUADS_PER_G (TOTAL_E / 4)       // 67584
#define EDGE_THREADS (2 * QUADS_PER_G)  // 135168

// ---------------- device scratch ----------------
__device__ __align__(128) float g_asrc[2][NA];
__device__ __align__(128) float g_adst[2][NA];
__device__ __align__(128) float g_den [2][NA];
__device__ __align__(128) float g_rden[2][NA];
__device__ __align__(128) float g_wsrc[2][NA];
__device__ __align__(128) float g_usrc[2][IN_DIM * NH];
__device__ __align__(128) float g_udst[2][IN_DIM * NH];
__device__ __align__(128) float g_G   [2][NH * IN_DIM];
__device__ __align__(128) float g_memb[2][HC];
__device__ int g_is64;

__device__ unsigned g_bar_count = 0;
__device__ unsigned g_bar_gen   = 0;
__device__ unsigned g_mb_count  = 0;   // 16-block tail mini-barrier
__device__ unsigned g_mb_gen    = 0;

__device__ __forceinline__ void red_add_v4(float* p, float a, float b, float c, float d) {
    asm volatile("red.global.add.v4.f32 [%0], {%1,%2,%3,%4};"
                 :: "l"(p), "f"(a), "f"(b), "f"(c), "f"(d) : "memory");
}
__device__ __forceinline__ void red_add_f(float* p, float a) {
    asm volatile("red.global.add.f32 [%0], %1;" :: "l"(p), "f"(a) : "memory");
}
__device__ __forceinline__ unsigned h2_ex2(unsigned v) {
    unsigned r;
    asm("ex2.approx.f16x2 %0, %1;" : "=r"(r) : "r"(v));
    return r;
}

__device__ __forceinline__ void grid_sync() {
    __threadfence();
    __syncthreads();
    if (threadIdx.x == 0) {
        unsigned gen = *(volatile unsigned*)&g_bar_gen;
        if (atomicAdd(&g_bar_count, 1u) == NBLK - 1) {
            g_bar_count = 0;
            __threadfence();
            *(volatile unsigned*)&g_bar_gen = gen + 1;
        } else {
            while (*(volatile unsigned*)&g_bar_gen == gen) __nanosleep(32);
        }
        __threadfence();
    }
    __syncthreads();
}

__device__ __forceinline__ void mini_sync16() {
    __threadfence();
    __syncthreads();
    if (threadIdx.x == 0) {
        unsigned gen = *(volatile unsigned*)&g_mb_gen;
        if (atomicAdd(&g_mb_count, 1u) == 15u) {
            g_mb_count = 0;
            __threadfence();
            *(volatile unsigned*)&g_mb_gen = gen + 1;
        } else {
            while (*(volatile unsigned*)&g_mb_gen == gen) __nanosleep(32);
        }
        __threadfence();
    }
    __syncthreads();
}

__global__ void __launch_bounds__(NTHR, 4)
k_all(const float* __restrict__ x1, const int* __restrict__ e1,
      const float* __restrict__ W1, const float* __restrict__ as1,
      const float* __restrict__ ad1, const float* __restrict__ b1,
      const float* __restrict__ x2, const int* __restrict__ e2,
      const float* __restrict__ W2, const float* __restrict__ as2,
      const float* __restrict__ ad2, const float* __restrict__ b2,
      const float* __restrict__ Wl, const float* __restrict__ bl,
      float* __restrict__ out) {
    __shared__ float sbuf[2304];
    const int tid  = threadIdx.x;
    const int b    = blockIdx.x;
    const int gtid = b * NTHR + tid;

    const int  eg    = (gtid >= QUADS_PER_G);
    const bool has_e = (gtid < EDGE_THREADS);
    const int  ebase = has_e ? (gtid - eg * QUADS_PER_G) * 4 : 0;
    const int* eptr  = eg ? e2 : e1;

    // ========== P0: zero scratch, detect dtype, u fold (scaled by log2e) ==========
    if (gtid < 2 * NA) {
        ((float*)g_den)[gtid]  = 0.0f;
        ((float*)g_wsrc)[gtid] = 0.0f;
    }
    if (gtid < 2 * NH * IN_DIM) ((float*)g_G)[gtid] = 0.0f;
    if (gtid < 256) out[gtid] = 0.0f;
    if (gtid == 0) {
        int all0 = 1;
        #pragma unroll
        for (int i = 0; i < 64; i++)
            if (e1[2 * i + 1] != 0) { all0 = 0; break; }
        g_is64 = all0;
    }
    {   // u[k][h] = log2e * sum_c W[k, h*128+c]*att[h,c]   (exp -> exp2 domain)
        int w = gtid >> 5, lane = gtid & 31;
        if (w < 512) {
            int g = w >> 8, which = (w >> 7) & 1, k = w & 127;
            const float* W   = g ? W2 : W1;
            const float* att = g ? (which ? ad2 : as2) : (which ? ad1 : as1);
            #pragma unroll
            for (int h = 0; h < 8; h++) {
                float4 wv = *reinterpret_cast<const float4*>(W + k * HC + h * 128 + lane * 4);
                float4 av = *reinterpret_cast<const float4*>(att + h * 128 + lane * 4);
                float s = wv.x * av.x + wv.y * av.y + wv.z * av.z + wv.w * av.w;
                #pragma unroll
                for (int off = 16; off; off >>= 1) s += __shfl_xor_sync(0xffffffffu, s, off);
                if (lane == 0) {
                    s *= 1.44269504f;
                    if (which) g_udst[g][k * NH + h] = s;
                    else       g_usrc[g][k * NH + h] = s;
                }
            }
        }
    }
    grid_sync();

    // ========== P1: a = x @ [usrc|udst], 2 threads per node, blocks 0..127 ==========
    if (b < 128) {
        int g = b >> 6;
        const float* x = g ? x2 : x1;
        for (int k = tid; k < IN_DIM; k += NTHR) {
            #pragma unroll
            for (int j = 0; j < 8; j++) {
                sbuf[k * 16 + j]     = g_usrc[g][k * 8 + j];
                sbuf[k * 16 + 8 + j] = g_udst[g][k * 8 + j];
            }
        }
        __syncthreads();
        int n    = (b & 63) * 128 + (tid >> 1);
        int kpar = tid & 1;
        const float* xr = x + n * IN_DIM;
        float acc[16];
        #pragma unroll
        for (int j = 0; j < 16; j++) acc[j] = 0.0f;
        #pragma unroll 8
        for (int j = 0; j < 64; j++) {
            int k = 2 * j + kpar;
            float xv = xr[k];
            const float* uk = sbuf + k * 16;
            #pragma unroll
            for (int q = 0; q < 16; q++) acc[q] += xv * uk[q];
        }
        #pragma unroll
        for (int q = 0; q < 16; q++) acc[q] += __shfl_xor_sync(0xffffffffu, acc[q], 1);
        if (kpar == 0) {
            float4* oa = reinterpret_cast<float4*>(g_asrc[g] + n * NH);
            oa[0] = make_float4(acc[0], acc[1], acc[2], acc[3]);
            oa[1] = make_float4(acc[4], acc[5], acc[6], acc[7]);
        } else {
            float4* od = reinterpret_cast<float4*>(g_adst[g] + n * NH);
            od[0] = make_float4(acc[8],  acc[9],  acc[10], acc[11]);
            od[1] = make_float4(acc[12], acc[13], acc[14], acc[15]);
        }
    }
    grid_sync();

    // ========== P2: edge pass 1: ex = exp2(lrelu(v)) in fp16x2; den += ex ==========
    int   esrc[EPT], edst[EPT];
    uint4 exh[EPT];
    if (has_e) {
        if (ebase < N_EDGES) {
            if (g_is64) {
                #pragma unroll
                for (int i = 0; i < EPT; i++) {
                    int2 sw = *reinterpret_cast<const int2*>(eptr + 2 * (ebase + i));
                    int2 dw = *reinterpret_cast<const int2*>(eptr + 2 * (N_EDGES + ebase + i));
                    esrc[i] = sw.x;
                    edst[i] = dw.x;
                }
            } else {
                #pragma unroll
                for (int i = 0; i < EPT; i++) {
                    esrc[i] = eptr[ebase + i];
                    edst[i] = eptr[N_EDGES + ebase + i];
                }
            }
        } else {
            #pragma unroll
            for (int i = 0; i < EPT; i++) esrc[i] = edst[i] = ebase - N_EDGES + i;
        }
        #pragma unroll
        for (int i = 0; i < EPT; i++) {
            const float4* as4 = reinterpret_cast<const float4*>(g_asrc[eg] + esrc[i] * NH);
            const float4* ad4 = reinterpret_cast<const float4*>(g_adst[eg] + edst[i] * NH);
            float4 s0 = as4[0], s1 = as4[1], d0 = ad4[0], d1 = ad4[1];
            float ev[8] = { s0.x + d0.x, s0.y + d0.y, s0.z + d0.z, s0.w + d0.w,
                            s1.x + d1.x, s1.y + d1.y, s1.z + d1.z, s1.w + d1.w };
            #pragma unroll
            for (int h = 0; h < 8; h++) {
                float v = ev[h];
                ev[h] = (v > 0.0f) ? v : 0.2f * v;   // lrelu commutes with log2e scale
            }
            unsigned hx[4];
            #pragma unroll
            for (int p = 0; p < 4; p++) {
                __half2 hv = __floats2half2_rn(ev[2*p], ev[2*p+1]);
                hx[p] = h2_ex2(*reinterpret_cast<unsigned*>(&hv));
            }
            exh[i] = make_uint4(hx[0], hx[1], hx[2], hx[3]);

            float ex[8];
            #pragma unroll
            for (int p = 0; p < 4; p++) {
                float2 f = __half22float2(*reinterpret_cast<const __half2*>(&hx[p]));
                ex[2*p] = f.x; ex[2*p+1] = f.y;
            }
            float* den = g_den[eg] + edst[i] * NH;
            red_add_v4(den,     ex[0], ex[1], ex[2], ex[3]);
            red_add_v4(den + 4, ex[4], ex[5], ex[6], ex[7]);
        }
    }
    grid_sync();

    // ========== P2.5: rden = 1/den ==========
    if (gtid < 2 * NA)
        ((float*)g_rden)[gtid] = __frcp_rn(((float*)g_den)[gtid]);
    grid_sync();

    // ========== P3: edge pass 2: Wsrc[src] += ex * rden[dst]  (MUFU-free) ==========
    if (has_e) {
        #pragma unroll
        for (int i = 0; i < EPT; i++) {
            const __half2* hx = reinterpret_cast<const __half2*>(&exh[i]);
            float ex[8];
            #pragma unroll
            for (int p = 0; p < 4; p++) {
                float2 f = __half22float2(hx[p]);
                ex[2*p] = f.x; ex[2*p+1] = f.y;
            }
            const float4* rd4 = reinterpret_cast<const float4*>(g_rden[eg] + edst[i] * NH);
            float4 r0 = rd4[0], r1 = rd4[1];
            float* ws = g_wsrc[eg] + esrc[i] * NH;
            red_add_v4(ws,     ex[0]*r0.x, ex[1]*r0.y, ex[2]*r0.z, ex[3]*r0.w);
            red_add_v4(ws + 4, ex[4]*r1.x, ex[5]*r1.y, ex[6]*r1.z, ex[7]*r1.w);
        }
    }
    grid_sync();

    // ========== P4: G[h,k] += sum_n Wsrc[n,h]*x[n,k], blocks 0..511 ==========
    if (b < 512) {
        int g  = b >> 8;
        int n0 = (b & 255) * 32;
        int k  = tid & 127, half = tid >> 7;
        const float* x = g ? x2 : x1;
        float acc[NH];
        #pragma unroll
        for (int h = 0; h < NH; h++) acc[h] = 0.0f;
        for (int i = half * 16; i < half * 16 + 16; i++) {
            int n = n0 + i;
            float xv = x[n * IN_DIM + k];
            const float4* w4 = reinterpret_cast<const float4*>(g_wsrc[g] + n * NH);
            float4 wa = w4[0], wb = w4[1];
            acc[0] += wa.x * xv; acc[1] += wa.y * xv; acc[2] += wa.z * xv; acc[3] += wa.w * xv;
            acc[4] += wb.x * xv; acc[5] += wb.y * xv; acc[6] += wb.z * xv; acc[7] += wb.w * xv;
        }
        #pragma unroll
        for (int h = 0; h < NH; h++) atomicAdd(&g_G[g][h * IN_DIM + k], acc[h]);
    }
    grid_sync();                    // last full-grid barrier
    if (b >= 16) return;            // only the 16 tail blocks continue

    // ========== P5a: memb[g][jc*128 .. +128), blocks 0..15 ==========
    {
        int g  = b >> 3;
        int jc = b & 7;
        const float* W  = g ? W2 : W1;
        const float* bb = g ? b2 : b1;
        float* sG   = sbuf;
        float* sred = sbuf + 128;
        if (tid < 128) sG[tid] = g_G[g][jc * 128 + tid];
        __syncthreads();
        int j = jc * 128 + (tid & 127);
        int kh = tid >> 7;
        float s = 0.0f;
        #pragma unroll 4
        for (int k = kh * 64; k < kh * 64 + 64; k++)
            s += sG[k] * W[k * HC + j];
        sred[tid] = s;
        __syncthreads();
        if (tid < 128)
            g_memb[g][j] = (sred[tid] + sred[tid + 128]) * (1.0f / N_NODES) + bb[j];
    }
    mini_sync16();

    // ========== P5b: out[s*128+c] += sum_{j chunk} memb[1-s][j]*Wl[j,c] ==========
    {
        int s  = b >> 3;
        int jc = b & 7;
        int g  = 1 - s;
        float* sm   = sbuf;
        float* sred = sbuf + 128;
        if (tid < 128) sm[tid] = g_memb[g][jc * 128 + tid];
        __syncthreads();
        int c  = tid & 127;
        int jh = tid >> 7;
        float acc = 0.0f;
        #pragma unroll 4
        for (int jl = jh * 64; jl < jh * 64 + 64; jl++)
            acc += sm[jl] * Wl[(jc * 128 + jl) * 128 + c];
        sred[tid] = acc;
        __syncthreads();
        if (tid < 128) {
            float v = sred[tid] + sred[tid + 128];
            if (jc == 0) v += bl[c];
            red_add_f(&out[s * 128 + c], v);
        }
    }
}

extern "C" void kernel_launch(void* const* d_in, const int* in_sizes, int n_in,
                              void* d_out, int out_size) {
    k_all<<<NBLK, NTHR>>>(
        (const float*)d_in[0],  (const int*)d_in[1],   (const float*)d_in[2],
        (const float*)d_in[3],  (const float*)d_in[4], (const float*)d_in[5],
        (const float*)d_in[6],  (const int*)d_in[7],   (const float*)d_in[8],
        (const float*)d_in[9],  (const float*)d_in[10],(const float*)d_in[11],
        (const float*)d_in[12], (const float*)d_in[13],
        (float*)d_out);
}

// round 10
// speedup vs baseline: 1.0237x; 1.0237x over previous
#include <cuda_runtime.h>
#include <cuda_fp16.h>

#define N_NODES 8192
#define N_EDGES 262144
#define NH 8
#define IN_DIM 128
#define HC 1024
#define TOTAL_E (N_EDGES + N_NODES)     // 270336, divisible by 4
#define NA (N_NODES * NH)

#define NBLK 592
#define NTHR 256
#define TOTNT (NBLK * NTHR)
#define EPT 4
#define QUADS_PER_G (TOTAL_E / 4)       // 67584
#define EDGE_THREADS (2 * QUADS_PER_G)  // 135168

// ---------------- device scratch ----------------
__device__ __align__(128) float g_asrc[2][NA];
__device__ __align__(128) float g_adst[2][NA];
__device__ __align__(128) float g_den [2][NA];
__device__ __align__(128) float g_wsrc[2][NA];
__device__ __align__(128) float g_usrc[2][IN_DIM * NH];
__device__ __align__(128) float g_udst[2][IN_DIM * NH];
__device__ __align__(128) float g_G   [2][NH * IN_DIM];
__device__ __align__(128) float g_memb[2][HC];
__device__ int g_is64;

__device__ unsigned g_bar_count = 0;
__device__ unsigned g_bar_gen   = 0;

__device__ __forceinline__ void red_add_v4(float* p, float a, float b, float c, float d) {
    asm volatile("red.global.add.v4.f32 [%0], {%1,%2,%3,%4};"
                 :: "l"(p), "f"(a), "f"(b), "f"(c), "f"(d) : "memory");
}
__device__ __forceinline__ void red_add_f(float* p, float a) {
    asm volatile("red.global.add.f32 [%0], %1;" :: "l"(p), "f"(a) : "memory");
}

__device__ __forceinline__ void grid_sync() {
    __threadfence();
    __syncthreads();
    if (threadIdx.x == 0) {
        unsigned gen = *(volatile unsigned*)&g_bar_gen;
        if (atomicAdd(&g_bar_count, 1u) == NBLK - 1) {
            g_bar_count = 0;
            __threadfence();
            *(volatile unsigned*)&g_bar_gen = gen + 1;
        } else {
            while (*(volatile unsigned*)&g_bar_gen == gen) __nanosleep(32);
        }
        __threadfence();
    }
    __syncthreads();
}

__global__ void __launch_bounds__(NTHR, 4)
k_all(const float* __restrict__ x1, const int* __restrict__ e1,
      const float* __restrict__ W1, const float* __restrict__ as1,
      const float* __restrict__ ad1, const float* __restrict__ b1,
      const float* __restrict__ x2, const int* __restrict__ e2,
      const float* __restrict__ W2, const float* __restrict__ as2,
      const float* __restrict__ ad2, const float* __restrict__ b2,
      const float* __restrict__ Wl, const float* __restrict__ bl,
      float* __restrict__ out) {
    __shared__ float sbuf[2304];
    const int tid  = threadIdx.x;
    const int b    = blockIdx.x;
    const int gtid = b * NTHR + tid;

    // edge ownership: 4 CONSECUTIVE edges of one graph per thread
    const int  eg    = (gtid >= QUADS_PER_G);
    const bool has_e = (gtid < EDGE_THREADS);
    const int  ebase = has_e ? (gtid - eg * QUADS_PER_G) * 4 : 0;
    const int* eptr  = eg ? e2 : e1;

    // ========== P0: zero scratch, detect dtype, u fold spread over 4096 warps ==========
    if (gtid < 2 * NA) {
        ((float*)g_den)[gtid]  = 0.0f;
        ((float*)g_wsrc)[gtid] = 0.0f;
    }
    if (gtid < 2 * NH * IN_DIM) ((float*)g_G)[gtid] = 0.0f;
    if (gtid < 256) out[gtid] = 0.0f;
    if (gtid == 0) {
        int all0 = 1;
        #pragma unroll
        for (int i = 0; i < 64; i++)
            if (e1[2 * i + 1] != 0) { all0 = 0; break; }
        g_is64 = all0;
    }
    {   // u[k][h] = sum_c W[k, h*128+c] * att[h,c] — one warp per (g,which,k,h)
        int w = gtid >> 5, lane = gtid & 31;
        if (w < 4096) {
            int g     = (w >> 11) & 1;
            int which = (w >> 10) & 1;
            int k     = (w >> 3) & 127;
            int h     = w & 7;
            const float* W   = g ? W2 : W1;
            const float* att = g ? (which ? ad2 : as2) : (which ? ad1 : as1);
            float4 wv = *reinterpret_cast<const float4*>(W + k * HC + h * 128 + lane * 4);
            float4 av = *reinterpret_cast<const float4*>(att + h * 128 + lane * 4);
            float s = wv.x * av.x + wv.y * av.y + wv.z * av.z + wv.w * av.w;
            #pragma unroll
            for (int off = 16; off; off >>= 1) s += __shfl_xor_sync(0xffffffffu, s, off);
            if (lane == 0) {
                if (which) g_udst[g][k * NH + h] = s;
                else       g_usrc[g][k * NH + h] = s;
            }
        }
    }
    grid_sync();

    // ========== P1: a = x @ [usrc|udst], 8 threads per node, blocks 0..511 ==========
    if (b < 512) {
        int g = b >> 8;
        const float* x = g ? x2 : x1;
        // stage u into shared: sbuf[k*16 + (0..7 src | 8..15 dst)]
        for (int k = tid; k < IN_DIM; k += NTHR) {
            #pragma unroll
            for (int j = 0; j < 8; j++) {
                sbuf[k * 16 + j]     = g_usrc[g][k * 8 + j];
                sbuf[k * 16 + 8 + j] = g_udst[g][k * 8 + j];
            }
        }
        __syncthreads();
        int n  = (b & 255) * 32 + (tid >> 3);    // 32 nodes per block
        int l8 = tid & 7;                        // 8 threads per node
        const float* xr = x + n * IN_DIM;
        float acc[16];
        #pragma unroll
        for (int q = 0; q < 16; q++) acc[q] = 0.0f;
        #pragma unroll
        for (int j = 0; j < 16; j++) {
            int k = j * 8 + l8;                  // consecutive lanes -> consecutive addrs
            float xv = xr[k];
            const float* uk = sbuf + k * 16;
            #pragma unroll
            for (int q = 0; q < 16; q++) acc[q] += xv * uk[q];
        }
        #pragma unroll
        for (int off = 4; off; off >>= 1) {
            #pragma unroll
            for (int q = 0; q < 16; q++)
                acc[q] += __shfl_xor_sync(0xffffffffu, acc[q], off);
        }
        if (l8 == 0) {
            float4* oa = reinterpret_cast<float4*>(g_asrc[g] + n * NH);
            float4* od = reinterpret_cast<float4*>(g_adst[g] + n * NH);
            oa[0] = make_float4(acc[0],  acc[1],  acc[2],  acc[3]);
            oa[1] = make_float4(acc[4],  acc[5],  acc[6],  acc[7]);
            od[0] = make_float4(acc[8],  acc[9],  acc[10], acc[11]);
            od[1] = make_float4(acc[12], acc[13], acc[14], acc[15]);
        }
    }
    grid_sync();

    // ========== P2: edge pass 1 (coalesced consecutive-edge index loads) ==========
    int   esrc[EPT], edst[EPT];
    uint4 exh[EPT];
    if (has_e) {
        if (ebase < N_EDGES) {
            if (g_is64) {
                #pragma unroll
                for (int i = 0; i < EPT; i++) {
                    int2 sw = *reinterpret_cast<const int2*>(eptr + 2 * (ebase + i));
                    int2 dw = *reinterpret_cast<const int2*>(eptr + 2 * (N_EDGES + ebase + i));
                    esrc[i] = sw.x;
                    edst[i] = dw.x;
                }
            } else {
                #pragma unroll
                for (int i = 0; i < EPT; i++) {
                    esrc[i] = eptr[ebase + i];
                    edst[i] = eptr[N_EDGES + ebase + i];
                }
            }
        } else {
            #pragma unroll
            for (int i = 0; i < EPT; i++) esrc[i] = edst[i] = ebase - N_EDGES + i;
        }
        #pragma unroll
        for (int i = 0; i < EPT; i++) {
            const float4* as4 = reinterpret_cast<const float4*>(g_asrc[eg] + esrc[i] * NH);
            const float4* ad4 = reinterpret_cast<const float4*>(g_adst[eg] + edst[i] * NH);
            float4 s0 = as4[0], s1 = as4[1], d0 = ad4[0], d1 = ad4[1];
            float ev[8] = { s0.x + d0.x, s0.y + d0.y, s0.z + d0.z, s0.w + d0.w,
                            s1.x + d1.x, s1.y + d1.y, s1.z + d1.z, s1.w + d1.w };
            float ex[8];
            #pragma unroll
            for (int h = 0; h < 8; h++) {
                float v = ev[h];
                v = (v > 0.0f) ? v : 0.2f * v;
                ex[h] = __expf(v);
            }
            __half2 hx[4];
            #pragma unroll
            for (int p = 0; p < 4; p++) hx[p] = __floats2half2_rn(ex[2*p], ex[2*p+1]);
            exh[i] = *reinterpret_cast<uint4*>(hx);

            float* den = g_den[eg] + edst[i] * NH;
            red_add_v4(den,     ex[0], ex[1], ex[2], ex[3]);
            red_add_v4(den + 4, ex[4], ex[5], ex[6], ex[7]);
        }
    }
    grid_sync();

    // ========== P3: edge pass 2: Wsrc[src] += ex / den[dst] ==========
    if (has_e) {
        #pragma unroll
        for (int i = 0; i < EPT; i++) {
            const __half2* hx = reinterpret_cast<const __half2*>(&exh[i]);
            float ex[8];
            #pragma unroll
            for (int p = 0; p < 4; p++) {
                float2 f = __half22float2(hx[p]);
                ex[2*p] = f.x; ex[2*p+1] = f.y;
            }
            const float4* dn4 = reinterpret_cast<const float4*>(g_den[eg] + edst[i] * NH);
            float4 n0 = dn4[0], n1 = dn4[1];
            float dn[8] = { n0.x, n0.y, n0.z, n0.w, n1.x, n1.y, n1.z, n1.w };
            float a[8];
            #pragma unroll
            for (int h = 0; h < 8; h++) a[h] = __fdividef(ex[h], dn[h]);
            float* ws = g_wsrc[eg] + esrc[i] * NH;
            red_add_v4(ws,     a[0], a[1], a[2], a[3]);
            red_add_v4(ws + 4, a[4], a[5], a[6], a[7]);
        }
    }
    grid_sync();

    // ========== P4: G[h,k] += sum_n Wsrc[n,h]*x[n,k], blocks 0..511 ==========
    if (b < 512) {
        int g  = b >> 8;
        int n0 = (b & 255) * 32;
        int k  = tid & 127, half = tid >> 7;
        const float* x = g ? x2 : x1;
        float acc[NH];
        #pragma unroll
        for (int h = 0; h < NH; h++) acc[h] = 0.0f;
        for (int i = half * 16; i < half * 16 + 16; i++) {
            int n = n0 + i;
            float xv = x[n * IN_DIM + k];
            const float4* w4 = reinterpret_cast<const float4*>(g_wsrc[g] + n * NH);
            float4 wa = w4[0], wb = w4[1];
            acc[0] += wa.x * xv; acc[1] += wa.y * xv; acc[2] += wa.z * xv; acc[3] += wa.w * xv;
            acc[4] += wb.x * xv; acc[5] += wb.y * xv; acc[6] += wb.z * xv; acc[7] += wb.w * xv;
        }
        #pragma unroll
        for (int h = 0; h < NH; h++) atomicAdd(&g_G[g][h * IN_DIM + k], acc[h]);
    }
    grid_sync();

    // ========== P5a: memb[g][jc*128 .. +128), blocks 0..15 ==========
    if (b < 16) {
        int g  = b >> 3;
        int jc = b & 7;
        const float* W  = g ? W2 : W1;
        const float* bb = g ? b2 : b1;
        float* sG   = sbuf;
        float* sred = sbuf + 128;
        if (tid < 128) sG[tid] = g_G[g][jc * 128 + tid];
        __syncthreads();
        int j = jc * 128 + (tid & 127);
        int kh = tid >> 7;
        float s = 0.0f;
        #pragma unroll 4
        for (int k = kh * 64; k < kh * 64 + 64; k++)
            s += sG[k] * W[k * HC + j];
        sred[tid] = s;
        __syncthreads();
        if (tid < 128)
            g_memb[g][j] = (sred[tid] + sred[tid + 128]) * (1.0f / N_NODES) + bb[j];
    }
    grid_sync();

    // ========== P5b: out[s*128+c] += sum_{j chunk} memb[1-s][j]*Wl[j,c], blocks 0..15 ==
    if (b < 16) {
        int s  = b >> 3;
        int jc = b & 7;
        int g  = 1 - s;
        float* sm   = sbuf;
        float* sred = sbuf + 128;
        if (tid < 128) sm[tid] = g_memb[g][jc * 128 + tid];
        __syncthreads();
        int c  = tid & 127;
        int jh = tid >> 7;
        float acc = 0.0f;
        #pragma unroll 4
        for (int jl = jh * 64; jl < jh * 64 + 64; jl++)
            acc += sm[jl] * Wl[(jc * 128 + jl) * 128 + c];
        sred[tid] = acc;
        __syncthreads();
        if (tid < 128) {
            float v = sred[tid] + sred[tid + 128];
            if (jc == 0) v += bl[c];
            red_add_f(&out[s * 128 + c], v);
        }
    }
}

extern "C" void kernel_launch(void* const* d_in, const int* in_sizes, int n_in,
                              void* d_out, int out_size) {
    k_all<<<NBLK, NTHR>>>(
        (const float*)d_in[0],  (const int*)d_in[1],   (const float*)d_in[2],
        (const float*)d_in[3],  (const float*)d_in[4], (const float*)d_in[5],
        (const float*)d_in[6],  (const int*)d_in[7],   (const float*)d_in[8],
        (const float*)d_in[9],  (const float*)d_in[10],(const float*)d_in[11],
        (const float*)d_in[12], (const float*)d_in[13],
        (float*)d_out);
}

// round 11
// speedup vs baseline: 1.0541x; 1.0296x over previous
#include <cuda_runtime.h>
#include <cuda_fp16.h>

#define N_NODES 8192
#define N_EDGES 262144
#define NH 8
#define IN_DIM 128
#define HC 1024
#define TOTAL_E (N_EDGES + N_NODES)     // 270336, divisible by 4
#define NA (N_NODES * NH)

#define NBLK 592
#define NTHR 256
#define TOTNT (NBLK * NTHR)
#define EPT 4
#define QUADS_PER_G (TOTAL_E / 4)       // 67584
#define EDGE_THREADS (2 * QUADS_PER_G)  // 135168

// ---------------- device scratch ----------------
__device__ __align__(128) __half g_as16[2][NA];   // a_src, fp16 (16B per node)
__device__ __align__(128) __half g_ad16[2][NA];   // a_dst, fp16
__device__ __align__(128) float g_den [2][NA];
__device__ __align__(128) float g_wsrc[2][NA];
__device__ __align__(128) float g_usrc[2][IN_DIM * NH];
__device__ __align__(128) float g_udst[2][IN_DIM * NH];
__device__ __align__(128) float g_G   [2][NH * IN_DIM];
__device__ __align__(128) float g_memb[2][HC];
__device__ int g_is64;

__device__ unsigned g_bar_count = 0;
__device__ unsigned g_bar_gen   = 0;

__device__ __forceinline__ void red_add_v4(float* p, float a, float b, float c, float d) {
    asm volatile("red.global.add.v4.f32 [%0], {%1,%2,%3,%4};"
                 :: "l"(p), "f"(a), "f"(b), "f"(c), "f"(d) : "memory");
}
__device__ __forceinline__ void red_add_f(float* p, float a) {
    asm volatile("red.global.add.f32 [%0], %1;" :: "l"(p), "f"(a) : "memory");
}

__device__ __forceinline__ void grid_sync() {
    __threadfence();
    __syncthreads();
    if (threadIdx.x == 0) {
        unsigned gen = *(volatile unsigned*)&g_bar_gen;
        if (atomicAdd(&g_bar_count, 1u) == NBLK - 1) {
            g_bar_count = 0;
            __threadfence();
            *(volatile unsigned*)&g_bar_gen = gen + 1;
        } else {
            while (*(volatile unsigned*)&g_bar_gen == gen) __nanosleep(32);
        }
        __threadfence();
    }
    __syncthreads();
}

__global__ void __launch_bounds__(NTHR, 4)
k_all(const float* __restrict__ x1, const int* __restrict__ e1,
      const float* __restrict__ W1, const float* __restrict__ as1,
      const float* __restrict__ ad1, const float* __restrict__ b1,
      const float* __restrict__ x2, const int* __restrict__ e2,
      const float* __restrict__ W2, const float* __restrict__ as2,
      const float* __restrict__ ad2, const float* __restrict__ b2,
      const float* __restrict__ Wl, const float* __restrict__ bl,
      float* __restrict__ out) {
    __shared__ float sbuf[2304];
    const int tid  = threadIdx.x;
    const int b    = blockIdx.x;
    const int gtid = b * NTHR + tid;

    // edge ownership: 4 CONSECUTIVE edges of one graph per thread
    const int  eg    = (gtid >= QUADS_PER_G);
    const bool has_e = (gtid < EDGE_THREADS);
    const int  ebase = has_e ? (gtid - eg * QUADS_PER_G) * 4 : 0;
    const int* eptr  = eg ? e2 : e1;

    // ========== P0: zero scratch, zero out, dtype detect, u fold ==========
    if (gtid < 2 * NA) {
        ((float*)g_den)[gtid]  = 0.0f;
        ((float*)g_wsrc)[gtid] = 0.0f;
    }
    if (gtid < 2 * NH * IN_DIM) ((float*)g_G)[gtid] = 0.0f;
    if (gtid < 256) out[gtid] = 0.0f;
    if (gtid == 0) {
        int all0 = 1;
        #pragma unroll
        for (int i = 0; i < 64; i++)
            if (e1[2 * i + 1] != 0) { all0 = 0; break; }
        g_is64 = all0;
    }
    {   // u[k][h] = sum_c W[k, h*128+c] * att[h,c]  — warp per (g,which,k)
        int w = gtid >> 5, lane = gtid & 31;
        if (w < 512) {
            int g = w >> 8, which = (w >> 7) & 1, k = w & 127;
            const float* W   = g ? W2 : W1;
            const float* att = g ? (which ? ad2 : as2) : (which ? ad1 : as1);
            #pragma unroll
            for (int h = 0; h < 8; h++) {
                float4 wv = *reinterpret_cast<const float4*>(W + k * HC + h * 128 + lane * 4);
                float4 av = *reinterpret_cast<const float4*>(att + h * 128 + lane * 4);
                float s = wv.x * av.x + wv.y * av.y + wv.z * av.z + wv.w * av.w;
                #pragma unroll
                for (int off = 16; off; off >>= 1) s += __shfl_xor_sync(0xffffffffu, s, off);
                if (lane == 0) {
                    if (which) g_udst[g][k * NH + h] = s;
                    else       g_usrc[g][k * NH + h] = s;
                }
            }
        }
    }
    grid_sync();

    // ========== P1: a = x @ [usrc|udst], 2 threads per node, blocks 0..127 ==========
    if (b < 128) {
        int g = b >> 6;
        const float* x = g ? x2 : x1;
        for (int k = tid; k < IN_DIM; k += NTHR) {
            #pragma unroll
            for (int j = 0; j < 8; j++) {
                sbuf[k * 16 + j]     = g_usrc[g][k * 8 + j];
                sbuf[k * 16 + 8 + j] = g_udst[g][k * 8 + j];
            }
        }
        __syncthreads();
        int n    = (b & 63) * 128 + (tid >> 1);
        int kpar = tid & 1;
        const float* xr = x + n * IN_DIM;
        float acc[16];
        #pragma unroll
        for (int j = 0; j < 16; j++) acc[j] = 0.0f;
        #pragma unroll 8
        for (int j = 0; j < 64; j++) {
            int k = 2 * j + kpar;
            float xv = xr[k];
            const float* uk = sbuf + k * 16;
            #pragma unroll
            for (int q = 0; q < 16; q++) acc[q] += xv * uk[q];
        }
        #pragma unroll
        for (int q = 0; q < 16; q++) acc[q] += __shfl_xor_sync(0xffffffffu, acc[q], 1);
        // pack to fp16: kpar==0 stores a_src (acc[0..7]); kpar==1 stores a_dst (acc[8..15])
        if (kpar == 0) {
            __half2 h[4];
            #pragma unroll
            for (int p = 0; p < 4; p++) h[p] = __floats2half2_rn(acc[2*p], acc[2*p+1]);
            *reinterpret_cast<uint4*>(g_as16[g] + n * NH) = *reinterpret_cast<uint4*>(h);
        } else {
            __half2 h[4];
            #pragma unroll
            for (int p = 0; p < 4; p++) h[p] = __floats2half2_rn(acc[8+2*p], acc[9+2*p]);
            *reinterpret_cast<uint4*>(g_ad16[g] + n * NH) = *reinterpret_cast<uint4*>(h);
        }
    }
    grid_sync();

    // ========== P2: edge pass 1 (fp16 16B gathers) ==========
    int   esrc[EPT], edst[EPT];
    uint4 exh[EPT];
    if (has_e) {
        if (ebase < N_EDGES) {
            if (g_is64) {
                #pragma unroll
                for (int i = 0; i < EPT; i++) {
                    int2 sw = *reinterpret_cast<const int2*>(eptr + 2 * (ebase + i));
                    int2 dw = *reinterpret_cast<const int2*>(eptr + 2 * (N_EDGES + ebase + i));
                    esrc[i] = sw.x;
                    edst[i] = dw.x;
                }
            } else {
                #pragma unroll
                for (int i = 0; i < EPT; i++) {
                    esrc[i] = eptr[ebase + i];
                    edst[i] = eptr[N_EDGES + ebase + i];
                }
            }
        } else {
            #pragma unroll
            for (int i = 0; i < EPT; i++) esrc[i] = edst[i] = ebase - N_EDGES + i;
        }
        #pragma unroll
        for (int i = 0; i < EPT; i++) {
            uint4 sa = *reinterpret_cast<const uint4*>(g_as16[eg] + esrc[i] * NH);
            uint4 da = *reinterpret_cast<const uint4*>(g_ad16[eg] + edst[i] * NH);
            const __half2* sh = reinterpret_cast<const __half2*>(&sa);
            const __half2* dh = reinterpret_cast<const __half2*>(&da);
            float ev[8];
            #pragma unroll
            for (int p = 0; p < 4; p++) {
                float2 fs = __half22float2(sh[p]);
                float2 fd = __half22float2(dh[p]);
                ev[2*p]   = fs.x + fd.x;
                ev[2*p+1] = fs.y + fd.y;
            }
            float ex[8];
            #pragma unroll
            for (int h = 0; h < 8; h++) {
                float v = ev[h];
                v = (v > 0.0f) ? v : 0.2f * v;
                ex[h] = __expf(v);
            }
            __half2 hx[4];
            #pragma unroll
            for (int p = 0; p < 4; p++) hx[p] = __floats2half2_rn(ex[2*p], ex[2*p+1]);
            exh[i] = *reinterpret_cast<uint4*>(hx);

            float* den = g_den[eg] + edst[i] * NH;
            red_add_v4(den,     ex[0], ex[1], ex[2], ex[3]);
            red_add_v4(den + 4, ex[4], ex[5], ex[6], ex[7]);
        }
    }
    grid_sync();

    // ========== P3: edge pass 2: Wsrc[src] += ex / den[dst] ==========
    if (has_e) {
        #pragma unroll
        for (int i = 0; i < EPT; i++) {
            const __half2* hx = reinterpret_cast<const __half2*>(&exh[i]);
            float ex[8];
            #pragma unroll
            for (int p = 0; p < 4; p++) {
                float2 f = __half22float2(hx[p]);
                ex[2*p] = f.x; ex[2*p+1] = f.y;
            }
            const float4* dn4 = reinterpret_cast<const float4*>(g_den[eg] + edst[i] * NH);
            float4 n0 = dn4[0], n1 = dn4[1];
            float dn[8] = { n0.x, n0.y, n0.z, n0.w, n1.x, n1.y, n1.z, n1.w };
            float a[8];
            #pragma unroll
            for (int h = 0; h < 8; h++) a[h] = __fdividef(ex[h], dn[h]);
            float* ws = g_wsrc[eg] + esrc[i] * NH;
            red_add_v4(ws,     a[0], a[1], a[2], a[3]);
            red_add_v4(ws + 4, a[4], a[5], a[6], a[7]);
        }
    }
    grid_sync();

    // ========== P4: G[h,k] += sum_n Wsrc[n,h]*x[n,k], blocks 0..511 ==========
    if (b < 512) {
        int g  = b >> 8;
        int n0 = (b & 255) * 32;
        int k  = tid & 127, half = tid >> 7;
        const float* x = g ? x2 : x1;
        float acc[NH];
        #pragma unroll
        for (int h = 0; h < NH; h++) acc[h] = 0.0f;
        for (int i = half * 16; i < half * 16 + 16; i++) {
            int n = n0 + i;
            float xv = x[n * IN_DIM + k];
            const float4* w4 = reinterpret_cast<const float4*>(g_wsrc[g] + n * NH);
            float4 wa = w4[0], wb = w4[1];
            acc[0] += wa.x * xv; acc[1] += wa.y * xv; acc[2] += wa.z * xv; acc[3] += wa.w * xv;
            acc[4] += wb.x * xv; acc[5] += wb.y * xv; acc[6] += wb.z * xv; acc[7] += wb.w * xv;
        }
        #pragma unroll
        for (int h = 0; h < NH; h++) atomicAdd(&g_G[g][h * IN_DIM + k], acc[h]);
    }
    grid_sync();

    // ========== P5a: memb[g][jc*128 .. +128), blocks 0..15 ==========
    if (b < 16) {
        int g  = b >> 3;
        int jc = b & 7;
        const float* W  = g ? W2 : W1;
        const float* bb = g ? b2 : b1;
        float* sG   = sbuf;
        float* sred = sbuf + 128;
        if (tid < 128) sG[tid] = g_G[g][jc * 128 + tid];
        __syncthreads();
        int j = jc * 128 + (tid & 127);
        int kh = tid >> 7;
        float s = 0.0f;
        #pragma unroll 4
        for (int k = kh * 64; k < kh * 64 + 64; k++)
            s += sG[k] * W[k * HC + j];
        sred[tid] = s;
        __syncthreads();
        if (tid < 128)
            g_memb[g][j] = (sred[tid] + sred[tid + 128]) * (1.0f / N_NODES) + bb[j];
    }
    grid_sync();

    // ========== P5b: out[s*128+c] += sum_{j chunk} memb[1-s][j]*Wl[j,c], blocks 0..15 ==
    if (b < 16) {
        int s  = b >> 3;
        int jc = b & 7;
        int g  = 1 - s;
        float* sm   = sbuf;
        float* sred = sbuf + 128;
        if (tid < 128) sm[tid] = g_memb[g][jc * 128 + tid];
        __syncthreads();
        int c  = tid & 127;
        int jh = tid >> 7;
        float acc = 0.0f;
        #pragma unroll 4
        for (int jl = jh * 64; jl < jh * 64 + 64; jl++)
            acc += sm[jl] * Wl[(jc * 128 + jl) * 128 + c];
        sred[tid] = acc;
        __syncthreads();
        if (tid < 128) {
            float v = sred[tid] + sred[tid + 128];
            if (jc == 0) v += bl[c];
            red_add_f(&out[s * 128 + c], v);
        }
    }
}

extern "C" void kernel_launch(void* const* d_in, const int* in_sizes, int n_in,
                              void* d_out, int out_size) {
    k_all<<<NBLK, NTHR>>>(
        (const float*)d_in[0],  (const int*)d_in[1],   (const float*)d_in[2],
        (const float*)d_in[3],  (const float*)d_in[4], (const float*)d_in[5],
        (const float*)d_in[6],  (const int*)d_in[7],   (const float*)d_in[8],
        (const float*)d_in[9],  (const float*)d_in[10],(const float*)d_in[11],
        (const float*)d_in[12], (const float*)d_in[13],
        (float*)d_out);
}

// round 12
// speedup vs baseline: 1.1210x; 1.0635x over previous
#include <cuda_runtime.h>
#include <cuda_fp16.h>

#define N_NODES 8192
#define N_EDGES 262144
#define NH 8
#define IN_DIM 128
#define HC 1024
#define TOTAL_E (N_EDGES + N_NODES)     // 270336, divisible by 4
#define NA (N_NODES * NH)

#define NBLK 592
#define NTHR 256
#define TOTNT (NBLK * NTHR)
#define EPT 4
#define QUADS_PER_G (TOTAL_E / 4)       // 67584
#define EDGE_THREADS (2 * QUADS_PER_G)  // 135168

// ---------------- device scratch ----------------
__device__ __align__(128) float g_asrc[2][NA];
__device__ __align__(128) float g_adst[2][NA];
__device__ __align__(128) float g_den [2][NA];
__device__ __align__(128) float g_wsrc[2][NA];
__device__ __align__(128) float g_usrc[2][IN_DIM * NH];
__device__ __align__(128) float g_udst[2][IN_DIM * NH];
__device__ __align__(128) float g_G   [2][NH * IN_DIM];
__device__ __align__(128) float g_memb[2][HC];
__device__ int g_is64;

__device__ unsigned g_bar_count = 0;
__device__ unsigned g_bar_gen   = 0;
__device__ unsigned g_mb_count  = 0;   // 16-block tail mini-barrier
__device__ unsigned g_mb_gen    = 0;

__device__ __forceinline__ void red_add_v4(float* p, float a, float b, float c, float d) {
    asm volatile("red.global.add.v4.f32 [%0], {%1,%2,%3,%4};"
                 :: "l"(p), "f"(a), "f"(b), "f"(c), "f"(d) : "memory");
}
__device__ __forceinline__ void red_add_f(float* p, float a) {
    asm volatile("red.global.add.f32 [%0], %1;" :: "l"(p), "f"(a) : "memory");
}

__device__ __forceinline__ void grid_sync() {
    __threadfence();
    __syncthreads();
    if (threadIdx.x == 0) {
        unsigned gen = *(volatile unsigned*)&g_bar_gen;
        if (atomicAdd(&g_bar_count, 1u) == NBLK - 1) {
            g_bar_count = 0;
            __threadfence();
            *(volatile unsigned*)&g_bar_gen = gen + 1;
        } else {
            while (*(volatile unsigned*)&g_bar_gen == gen) __nanosleep(32);
        }
        __threadfence();
    }
    __syncthreads();
}

__device__ __forceinline__ void mini_sync16() {
    __threadfence();
    __syncthreads();
    if (threadIdx.x == 0) {
        unsigned gen = *(volatile unsigned*)&g_mb_gen;
        if (atomicAdd(&g_mb_count, 1u) == 15u) {
            g_mb_count = 0;
            __threadfence();
            *(volatile unsigned*)&g_mb_gen = gen + 1;
        } else {
            while (*(volatile unsigned*)&g_mb_gen == gen) __nanosleep(32);
        }
        __threadfence();
    }
    __syncthreads();
}

__global__ void __launch_bounds__(NTHR, 4)
k_all(const float* __restrict__ x1, const int* __restrict__ e1,
      const float* __restrict__ W1, const float* __restrict__ as1,
      const float* __restrict__ ad1, const float* __restrict__ b1,
      const float* __restrict__ x2, const int* __restrict__ e2,
      const float* __restrict__ W2, const float* __restrict__ as2,
      const float* __restrict__ ad2, const float* __restrict__ b2,
      const float* __restrict__ Wl, const float* __restrict__ bl,
      float* __restrict__ out) {
    __shared__ float sbuf[2304];
    const int tid  = threadIdx.x;
    const int b    = blockIdx.x;
    const int gtid = b * NTHR + tid;

    // edge ownership: 4 CONSECUTIVE edges of one graph per thread
    const int  eg    = (gtid >= QUADS_PER_G);
    const bool has_e = (gtid < EDGE_THREADS);
    const int  ebase = has_e ? (gtid - eg * QUADS_PER_G) * 4 : 0;
    const int* eptr  = eg ? e2 : e1;

    // ========== P0: zero scratch, zero out, dtype detect, u fold ==========
    if (gtid < 2 * NA) {
        ((float*)g_den)[gtid]  = 0.0f;
        ((float*)g_wsrc)[gtid] = 0.0f;
    }
    if (gtid < 2 * NH * IN_DIM) ((float*)g_G)[gtid] = 0.0f;
    if (gtid < 256) out[gtid] = 0.0f;
    if (gtid == 0) {
        int all0 = 1;
        #pragma unroll
        for (int i = 0; i < 64; i++)
            if (e1[2 * i + 1] != 0) { all0 = 0; break; }
        g_is64 = all0;
    }
    {   // u[k][h] = sum_c W[k, h*128+c] * att[h,c]  — warp per (g,which,k)
        int w = gtid >> 5, lane = gtid & 31;
        if (w < 512) {
            int g = w >> 8, which = (w >> 7) & 1, k = w & 127;
            const float* W   = g ? W2 : W1;
            const float* att = g ? (which ? ad2 : as2) : (which ? ad1 : as1);
            #pragma unroll
            for (int h = 0; h < 8; h++) {
                float4 wv = *reinterpret_cast<const float4*>(W + k * HC + h * 128 + lane * 4);
                float4 av = *reinterpret_cast<const float4*>(att + h * 128 + lane * 4);
                float s = wv.x * av.x + wv.y * av.y + wv.z * av.z + wv.w * av.w;
                #pragma unroll
                for (int off = 16; off; off >>= 1) s += __shfl_xor_sync(0xffffffffu, s, off);
                if (lane == 0) {
                    if (which) g_udst[g][k * NH + h] = s;
                    else       g_usrc[g][k * NH + h] = s;
                }
            }
        }
    }
    grid_sync();

    // ========== P1: a = x @ [usrc|udst], 2 threads per node, blocks 0..127 ==========
    if (b < 128) {
        int g = b >> 6;
        const float* x = g ? x2 : x1;
        for (int k = tid; k < IN_DIM; k += NTHR) {
            #pragma unroll
            for (int j = 0; j < 8; j++) {
                sbuf[k * 16 + j]     = g_usrc[g][k * 8 + j];
                sbuf[k * 16 + 8 + j] = g_udst[g][k * 8 + j];
            }
        }
        __syncthreads();
        int n    = (b & 63) * 128 + (tid >> 1);
        int kpar = tid & 1;
        const float* xr = x + n * IN_DIM;
        float acc[16];
        #pragma unroll
        for (int j = 0; j < 16; j++) acc[j] = 0.0f;
        #pragma unroll 8
        for (int j = 0; j < 64; j++) {
            int k = 2 * j + kpar;
            float xv = xr[k];
            const float* uk = sbuf + k * 16;
            #pragma unroll
            for (int q = 0; q < 16; q++) acc[q] += xv * uk[q];
        }
        #pragma unroll
        for (int q = 0; q < 16; q++) acc[q] += __shfl_xor_sync(0xffffffffu, acc[q], 1);
        if (kpar == 0) {
            float4* oa = reinterpret_cast<float4*>(g_asrc[g] + n * NH);
            oa[0] = make_float4(acc[0], acc[1], acc[2], acc[3]);
            oa[1] = make_float4(acc[4], acc[5], acc[6], acc[7]);
        } else {
            float4* od = reinterpret_cast<float4*>(g_adst[g] + n * NH);
            od[0] = make_float4(acc[8],  acc[9],  acc[10], acc[11]);
            od[1] = make_float4(acc[12], acc[13], acc[14], acc[15]);
        }
    }
    grid_sync();

    // ========== P2: edge pass 1 (coalesced consecutive-edge index loads) ==========
    int   esrc[EPT], edst[EPT];
    uint4 exh[EPT];
    if (has_e) {
        if (ebase < N_EDGES) {
            if (g_is64) {
                #pragma unroll
                for (int i = 0; i < EPT; i++) {
                    int2 sw = *reinterpret_cast<const int2*>(eptr + 2 * (ebase + i));
                    int2 dw = *reinterpret_cast<const int2*>(eptr + 2 * (N_EDGES + ebase + i));
                    esrc[i] = sw.x;
                    edst[i] = dw.x;
                }
            } else {
                #pragma unroll
                for (int i = 0; i < EPT; i++) {
                    esrc[i] = eptr[ebase + i];
                    edst[i] = eptr[N_EDGES + ebase + i];
                }
            }
        } else {
            #pragma unroll
            for (int i = 0; i < EPT; i++) esrc[i] = edst[i] = ebase - N_EDGES + i;
        }
        #pragma unroll
        for (int i = 0; i < EPT; i++) {
            const float4* as4 = reinterpret_cast<const float4*>(g_asrc[eg] + esrc[i] * NH);
            const float4* ad4 = reinterpret_cast<const float4*>(g_adst[eg] + edst[i] * NH);
            float4 s0 = as4[0], s1 = as4[1], d0 = ad4[0], d1 = ad4[1];
            float ev[8] = { s0.x + d0.x, s0.y + d0.y, s0.z + d0.z, s0.w + d0.w,
                            s1.x + d1.x, s1.y + d1.y, s1.z + d1.z, s1.w + d1.w };
            float ex[8];
            #pragma unroll
            for (int h = 0; h < 8; h++) {
                float v = ev[h];
                v = (v > 0.0f) ? v : 0.2f * v;
                ex[h] = __expf(v);
            }
            __half2 hx[4];
            #pragma unroll
            for (int p = 0; p < 4; p++) hx[p] = __floats2half2_rn(ex[2*p], ex[2*p+1]);
            exh[i] = *reinterpret_cast<uint4*>(hx);

            float* den = g_den[eg] + edst[i] * NH;
            red_add_v4(den,     ex[0], ex[1], ex[2], ex[3]);
            red_add_v4(den + 4, ex[4], ex[5], ex[6], ex[7]);
        }
    }
    grid_sync();

    // ========== P3: edge pass 2: Wsrc[src] += ex / den[dst] ==========
    if (has_e) {
        #pragma unroll
        for (int i = 0; i < EPT; i++) {
            const __half2* hx = reinterpret_cast<const __half2*>(&exh[i]);
            float ex[8];
            #pragma unroll
            for (int p = 0; p < 4; p++) {
                float2 f = __half22float2(hx[p]);
                ex[2*p] = f.x; ex[2*p+1] = f.y;
            }
            const float4* dn4 = reinterpret_cast<const float4*>(g_den[eg] + edst[i] * NH);
            float4 n0 = dn4[0], n1 = dn4[1];
            float dn[8] = { n0.x, n0.y, n0.z, n0.w, n1.x, n1.y, n1.z, n1.w };
            float a[8];
            #pragma unroll
            for (int h = 0; h < 8; h++) a[h] = __fdividef(ex[h], dn[h]);
            float* ws = g_wsrc[eg] + esrc[i] * NH;
            red_add_v4(ws,     a[0], a[1], a[2], a[3]);
            red_add_v4(ws + 4, a[4], a[5], a[6], a[7]);
        }
    }
    grid_sync();

    // ========== P4: G[h,k] += sum_n Wsrc[n,h]*x[n,k], blocks 0..511 ==========
    if (b < 512) {
        int g  = b >> 8;
        int n0 = (b & 255) * 32;
        int k  = tid & 127, half = tid >> 7;
        const float* x = g ? x2 : x1;
        float acc[NH];
        #pragma unroll
        for (int h = 0; h < NH; h++) acc[h] = 0.0f;
        for (int i = half * 16; i < half * 16 + 16; i++) {
            int n = n0 + i;
            float xv = x[n * IN_DIM + k];
            const float4* w4 = reinterpret_cast<const float4*>(g_wsrc[g] + n * NH);
            float4 wa = w4[0], wb = w4[1];
            acc[0] += wa.x * xv; acc[1] += wa.y * xv; acc[2] += wa.z * xv; acc[3] += wa.w * xv;
            acc[4] += wb.x * xv; acc[5] += wb.y * xv; acc[6] += wb.z * xv; acc[7] += wb.w * xv;
        }
        #pragma unroll
        for (int h = 0; h < NH; h++) atomicAdd(&g_G[g][h * IN_DIM + k], acc[h]);
    }
    grid_sync();                    // last full-grid barrier
    if (b >= 16) return;            // 576 blocks retire here

    // ========== P5a: memb[g][jc*128 .. +128), blocks 0..15 ==========
    {
        int g  = b >> 3;
        int jc = b & 7;
        const float* W  = g ? W2 : W1;
        const float* bb = g ? b2 : b1;
        float* sG   = sbuf;
        float* sred = sbuf + 128;
        if (tid < 128) sG[tid] = g_G[g][jc * 128 + tid];
        __syncthreads();
        int j = jc * 128 + (tid & 127);
        int kh = tid >> 7;
        float s = 0.0f;
        #pragma unroll 4
        for (int k = kh * 64; k < kh * 64 + 64; k++)
            s += sG[k] * W[k * HC + j];
        sred[tid] = s;
        __syncthreads();
        if (tid < 128)
            g_memb[g][j] = (sred[tid] + sred[tid + 128]) * (1.0f / N_NODES) + bb[j];
    }
    mini_sync16();

    // ========== P5b: out[s*128+c] += sum_{j chunk} memb[1-s][j]*Wl[j,c] ==========
    {
        int s  = b >> 3;
        int jc = b & 7;
        int g  = 1 - s;
        float* sm   = sbuf;
        float* sred = sbuf + 128;
        if (tid < 128) sm[tid] = g_memb[g][jc * 128 + tid];
        __syncthreads();
        int c  = tid & 127;
        int jh = tid >> 7;
        float acc = 0.0f;
        #pragma unroll 4
        for (int jl = jh * 64; jl < jh * 64 + 64; jl++)
            acc += sm[jl] * Wl[(jc * 128 + jl) * 128 + c];
        sred[tid] = acc;
        __syncthreads();
        if (tid < 128) {
            float v = sred[tid] + sred[tid + 128];
            if (jc == 0) v += bl[c];
            red_add_f(&out[s * 128 + c], v);
        }
    }
}

extern "C" void kernel_launch(void* const* d_in, const int* in_sizes, int n_in,
                              void* d_out, int out_size) {
    k_all<<<NBLK, NTHR>>>(
        (const float*)d_in[0],  (const int*)d_in[1],   (const float*)d_in[2],
        (const float*)d_in[3],  (const float*)d_in[4], (const float*)d_in[5],
        (const float*)d_in[6],  (const int*)d_in[7],   (const float*)d_in[8],
        (const float*)d_in[9],  (const float*)d_in[10],(const float*)d_in[11],
        (const float*)d_in[12], (const float*)d_in[13],
        (float*)d_out);
}